// round 14
// baseline (speedup 1.0000x reference)
#include <cuda_runtime.h>
#include <cuda_bf16.h>
#include <cstdint>
#include <cstddef>
#include <math.h>

// Problem constants
#define BB 32
#define SS 512
#define DD 512
#define HH 512
#define G4 (4 * HH)     // 2048
#define NBLK 128        // persistent grid size (recurrence)
#define NBLK_DIR 64     // CTAs per direction
#define NT 512          // recurrence CTA threads

// ===========================================================================
// Small helpers
// ===========================================================================
__device__ __forceinline__ uint32_t smem_u32(const void* p)
{
    uint32_t a;
    asm("{ .reg .u64 t; cvta.to.shared.u64 t, %1; cvt.u32.u64 %0, t; }"
        : "=r"(a) : "l"(p));
    return a;
}

// ldmatrix x4 (four 8x8 b16 matrices)
__device__ __forceinline__ void ldsm4(uint32_t& r0, uint32_t& r1,
                                      uint32_t& r2, uint32_t& r3, uint32_t addr)
{
    asm volatile("ldmatrix.sync.aligned.m8n8.x4.shared.b16 {%0,%1,%2,%3}, [%4];"
                 : "=r"(r0), "=r"(r1), "=r"(r2), "=r"(r3) : "r"(addr));
}

// mma m16n8k16 bf16 -> f32
__device__ __forceinline__ void mma16816(float* c, const uint32_t* a,
                                         const uint32_t* b)
{
    asm volatile(
        "mma.sync.aligned.m16n8k16.row.col.f32.bf16.bf16.f32 "
        "{%0,%1,%2,%3}, {%4,%5,%6,%7}, {%8,%9}, {%0,%1,%2,%3};"
        : "+f"(c[0]), "+f"(c[1]), "+f"(c[2]), "+f"(c[3])
        : "r"(a[0]), "r"(a[1]), "r"(a[2]), "r"(a[3]), "r"(b[0]), "r"(b[1]));
}

__device__ __forceinline__ void cp_async16(uint32_t dst, const void* src)
{
    asm volatile("cp.async.cg.shared.global [%0], [%1], 16;"
                 :: "r"(dst), "l"(src) : "memory");
}

// Packed fp32x2 helpers (recurrence)
__device__ __forceinline__ void fma2(unsigned long long& d,
                                     unsigned long long a, unsigned long long b)
{
    asm("fma.rn.f32x2 %0, %1, %2, %0;" : "+l"(d) : "l"(a), "l"(b));
}
__device__ __forceinline__ float2 unpack2(unsigned long long v)
{
    float2 r;
    asm("mov.b64 {%0, %1}, %2;" : "=f"(r.x), "=f"(r.y) : "l"(v));
    return r;
}

// ===========================================================================
// Scratch (static __device__ arrays — no allocation allowed)
// ===========================================================================
__device__ float g_xp[2][SS][BB][G4];            // input projections [dir][s][b][g]
__device__ float g_out0[BB][SS][2 * HH];         // layer-0 output
__device__ float g_h[2][2][BB][HH];              // [dir][parity][b][h]
__device__ unsigned g_flags[2][NBLK_DIR];        // per-CTA step flags
__device__ __nv_bfloat16 g_a_hi[16384 * 1024];   // A hi (max K=1024)
__device__ __nv_bfloat16 g_a_lo[16384 * 1024];   // A lo
__device__ __nv_bfloat16 g_w_hi[2][G4 * 1024];   // W hi per direction
__device__ __nv_bfloat16 g_w_lo[2][G4 * 1024];   // W lo per direction

// ---------------------------------------------------------------------------
// Zero h state + step flags
// ---------------------------------------------------------------------------
__global__ void __launch_bounds__(256) init_state_kernel()
{
    int i = blockIdx.x * 256 + threadIdx.x;
    if (i < 2 * 2 * BB * HH) (&g_h[0][0][0][0])[i] = 0.0f;
    if (i < 2 * NBLK_DIR)    (&g_flags[0][0])[i] = 0u;
}

// ---------------------------------------------------------------------------
// fp32 -> bf16 (hi, lo) split: x ≈ hi + lo, lo = rn(x - hi)
// ---------------------------------------------------------------------------
__global__ void __launch_bounds__(256) conv_pair_kernel(
    const float* __restrict__ src,
    __nv_bfloat16* __restrict__ hi, __nv_bfloat16* __restrict__ lo, int n4)
{
    int i = blockIdx.x * 256 + threadIdx.x;
    if (i >= n4) return;
    float4 v = ((const float4*)src)[i];
    __nv_bfloat16 h0 = __float2bfloat16(v.x);
    __nv_bfloat16 h1 = __float2bfloat16(v.y);
    __nv_bfloat16 h2 = __float2bfloat16(v.z);
    __nv_bfloat16 h3 = __float2bfloat16(v.w);
    __nv_bfloat16 l0 = __float2bfloat16(v.x - __bfloat162float(h0));
    __nv_bfloat16 l1 = __float2bfloat16(v.y - __bfloat162float(h1));
    __nv_bfloat16 l2 = __float2bfloat16(v.z - __bfloat162float(h2));
    __nv_bfloat16 l3 = __float2bfloat16(v.w - __bfloat162float(h3));
    ((__nv_bfloat162*)hi)[2 * i]     = __halves2bfloat162(h0, h1);
    ((__nv_bfloat162*)hi)[2 * i + 1] = __halves2bfloat162(h2, h3);
    ((__nv_bfloat162*)lo)[2 * i]     = __halves2bfloat162(l0, l1);
    ((__nv_bfloat162*)lo)[2 * i + 1] = __halves2bfloat162(l2, l3);
}

// ===========================================================================
// Tensor-core GEMM via mma.sync (3xBF16)  — unchanged (passing, ~HMMA floor)
// ===========================================================================
#define KC 32
#define TSTB 80                              // smem row stride in BYTES
#define ATILE (128 * TSTB)                   // 10240 B (each of Ahi, Alo)
#define BTILE (256 * TSTB)                   // 20480 B (each of Bhi, Blo)
#define BUFB (2 * ATILE + 2 * BTILE)         // 61440 B
#define GSMEM (3 * BUFB)                     // 184320 B

__global__ void __launch_bounds__(256) gemm_tc_kernel(
    const __nv_bfloat16* __restrict__ Ahi, const __nv_bfloat16* __restrict__ Alo,
    const __nv_bfloat16* __restrict__ Whi, const __nv_bfloat16* __restrict__ Wlo,
    const float* __restrict__ bias, float* __restrict__ out, int K)
{
    extern __shared__ char smem[];
    const int tid = threadIdx.x;
    const int wid = tid >> 5, lane = tid & 31;
    const int wm = wid >> 2, wn = wid & 3;       // 2 x 4 warp grid
    const int m0 = blockIdx.y * 128, n0 = blockIdx.x * 256;
    const uint32_t sb = smem_u32(smem);
    const int nch = K / KC;

    const int srow = tid >> 1;                   // 0..127
    const int sj16 = (tid & 1) * 32;             // byte offset of 2-uint4 pair
    const __nv_bfloat16* gAh = Ahi + (size_t)m0 * K;
    const __nv_bfloat16* gAl = Alo + (size_t)m0 * K;
    const __nv_bfloat16* gBh = Whi + (size_t)n0 * K;
    const __nv_bfloat16* gBl = Wlo + (size_t)n0 * K;

    float acc[4][8][4];
#pragma unroll
    for (int i = 0; i < 4; i++)
#pragma unroll
        for (int j = 0; j < 8; j++)
#pragma unroll
            for (int r = 0; r < 4; r++) acc[i][j][r] = 0.0f;

    auto issue = [&](int c) {
        const uint32_t b0 = sb + (c % 3) * BUFB;
        const int ko = c * KC;
        {
            const uint32_t d = b0 + srow * TSTB + sj16;
            const size_t go = (size_t)srow * K + ko + (sj16 >> 1);
            cp_async16(d,              gAh + go);
            cp_async16(d + 16,         gAh + go + 8);
            cp_async16(d + ATILE,      gAl + go);
            cp_async16(d + ATILE + 16, gAl + go + 8);
        }
        {
            const uint32_t bh = b0 + 2 * ATILE;
#pragma unroll
            for (int pass = 0; pass < 2; pass++) {
                const int r = srow + pass * 128;
                const uint32_t d = bh + r * TSTB + sj16;
                const size_t go = (size_t)r * K + ko + (sj16 >> 1);
                cp_async16(d,              gBh + go);
                cp_async16(d + 16,         gBh + go + 8);
                cp_async16(d + BTILE,      gBl + go);
                cp_async16(d + BTILE + 16, gBl + go + 8);
            }
        }
        asm volatile("cp.async.commit_group;" ::: "memory");
    };

    issue(0);
    if (nch > 1) issue(1);
    if (nch > 2) issue(2);

    const uint32_t a_row = wm * 64 + (lane & 15);
    const uint32_t a_kb  = ((lane >> 4) * 8) * 2;
    const uint32_t b_n   = wn * 64 + ((lane >> 4) << 3) + (lane & 7);
    const uint32_t b_kb  = (((lane >> 3) & 1) * 8) * 2;

    for (int c = 0; c < nch; c++) {
        int pend = nch - 1 - c; if (pend > 2) pend = 2;
        if (pend == 2)      asm volatile("cp.async.wait_group 2;" ::: "memory");
        else if (pend == 1) asm volatile("cp.async.wait_group 1;" ::: "memory");
        else                asm volatile("cp.async.wait_group 0;" ::: "memory");
        __syncthreads();

        const uint32_t ah = sb + (c % 3) * BUFB;
        const uint32_t al = ah + ATILE;
        const uint32_t bh = ah + 2 * ATILE;
        const uint32_t bl = bh + BTILE;

#pragma unroll
        for (int kk = 0; kk < 2; kk++) {
            uint32_t Bh[16], Bl[16];
#pragma unroll
            for (int jj = 0; jj < 4; jj++) {
                uint32_t addr = (b_n + jj * 16) * TSTB + kk * 32 + b_kb;
                ldsm4(Bh[4 * jj], Bh[4 * jj + 1], Bh[4 * jj + 2], Bh[4 * jj + 3], bh + addr);
                ldsm4(Bl[4 * jj], Bl[4 * jj + 1], Bl[4 * jj + 2], Bl[4 * jj + 3], bl + addr);
            }
#pragma unroll
            for (int i = 0; i < 4; i++) {
                uint32_t addr = (a_row + i * 16) * TSTB + kk * 32 + a_kb;
                uint32_t Ah[4], Al[4];
                ldsm4(Ah[0], Ah[1], Ah[2], Ah[3], ah + addr);
                ldsm4(Al[0], Al[1], Al[2], Al[3], al + addr);
#pragma unroll
                for (int j = 0; j < 8; j++) {
                    mma16816(acc[i][j], Ah, Bh + 2 * j);
                    mma16816(acc[i][j], Ah, Bl + 2 * j);
                    mma16816(acc[i][j], Al, Bh + 2 * j);
                }
            }
        }
        __syncthreads();
        if (c + 3 < nch) issue(c + 3);
    }

#pragma unroll
    for (int i = 0; i < 4; i++) {
        const int r = m0 + wm * 64 + i * 16 + (lane >> 2);   // m = b*SS + s
        const int s_ = r & 511, b_ = r >> 9;
        float* p0 = out + ((size_t)s_ * BB + b_) * G4;
        float* p1 = p0 + (size_t)8 * BB * G4;
#pragma unroll
        for (int j = 0; j < 8; j++) {
            const int col = n0 + wn * 64 + j * 8 + (lane & 3) * 2;
            float2 bv = *(const float2*)(bias + col);
            float2 v0 = { acc[i][j][0] + bv.x, acc[i][j][1] + bv.y };
            float2 v1 = { acc[i][j][2] + bv.x, acc[i][j][3] + bv.y };
            *(float2*)(p0 + col) = v0;
            *(float2*)(p1 + col) = v1;
        }
    }
}

// ---------------------------------------------------------------------------
// Persistent per-layer LSTM recurrence. Flag-array barrier:
// arrivals are parallel STGs to distinct addresses (no atomic chain, no
// releaser hop); every CTA's threads 0..63 poll all 64 flags directly.
// Flags are monotonic step tags, zeroed by init_state_kernel per layer.
// ---------------------------------------------------------------------------
__device__ __forceinline__ float sigmoidf_(float x) { return 1.0f / (1.0f + expf(-x)); }

#define HST 516
#define WST 516
#define PST 260

__global__ void __launch_bounds__(NT) lstm_layer_kernel(
    const float* __restrict__ whh_f, const float* __restrict__ whh_b,
    float* __restrict__ outbuf)
{
    extern __shared__ float sm[];
    float* h_s = sm;                      // [32][HST]
    float* w_s = sm + 32 * HST;           // [32][WST]
    float* p_s = w_s + 32 * WST;          // [32][PST]

    const int dir  = blockIdx.x >> 6;
    const int cb   = blockIdx.x & 63;
    const int col0 = cb * 8;
    const int tid  = threadIdx.x;
    const float* whh = dir ? whh_b : whh_f;
    volatile unsigned* flags = (volatile unsigned*)&g_flags[dir][0];

    // ---- stage 32 weight rows ONCE: row r = gate*8 + cl ----
#pragma unroll
    for (int i = 0; i < 8; i++) {
        int n = tid + i * NT;
        int r = n >> 7, k4 = n & 127;
        int gate = r >> 3, cl = r & 7;
        float4 v = *(const float4*)(whh + ((size_t)gate * HH + col0 + cl) * HH + k4 * 4);
        *(float4*)(w_s + r * WST + k4 * 4) = v;
    }

    const int ks = tid >> 6;
    const int lo = tid & 63;
    const int bq = lo >> 3;
    const int rq = lo & 7;
    const int kk0 = ks * 16;

    const int ub = tid >> 3, ucl = tid & 7, ucol = col0 + ucl;
    float c_reg = 0.0f;
    const float* xbase = &g_xp[dir][0][0][0];

    for (int t = 0; t < SS; t++) {
        const int ph = t & 1;
        const int tt = dir ? (SS - 1 - t) : t;

        // ---- xp prefetch FIRST: DRAM fetch overlaps the flag wait ----
        float xi = 0.f, xf = 0.f, xg = 0.f, xo_ = 0.f;
        if (tid < 256) {
            const size_t xo = ((size_t)tt * BB + ub) * G4 + ucol;
            xi  = __ldg(xbase + xo);
            xf  = __ldg(xbase + xo + HH);
            xg  = __ldg(xbase + xo + 2 * HH);
            xo_ = __ldg(xbase + xo + 3 * HH);
        }

        // ---- wait: all 64 producer CTAs of this direction at step >= t ----
        if (tid < NBLK_DIR) {
            while (flags[tid] < (unsigned)t) { }
            __threadfence();              // acquire
        }
        __syncthreads();

        // ---- stage h_prev into padded smem (L2 loads bypass L1) ----
        {
            const float4* hp = (const float4*)&g_h[dir][ph][0][0];
#pragma unroll
            for (int i = 0; i < 8; i++) {
                int n = tid + i * NT;
                float4 v = __ldcg(hp + n);
                int b = n >> 7, k4 = n & 127;
                *(float4*)(h_s + b * HST + k4 * 4) = v;
            }
        }
        __syncthreads();

        // ---- 4x4 register micro-tile over this thread's k-eighth ----
        const ulonglong2* h0 = (const ulonglong2*)(h_s + (bq     ) * HST) + kk0;
        const ulonglong2* h1 = (const ulonglong2*)(h_s + (bq +  8) * HST) + kk0;
        const ulonglong2* h2 = (const ulonglong2*)(h_s + (bq + 16) * HST) + kk0;
        const ulonglong2* h3 = (const ulonglong2*)(h_s + (bq + 24) * HST) + kk0;
        const ulonglong2* w0 = (const ulonglong2*)(w_s + (rq     ) * WST) + kk0;
        const ulonglong2* w1 = (const ulonglong2*)(w_s + (rq +  8) * WST) + kk0;
        const ulonglong2* w2 = (const ulonglong2*)(w_s + (rq + 16) * WST) + kk0;
        const ulonglong2* w3 = (const ulonglong2*)(w_s + (rq + 24) * WST) + kk0;

        unsigned long long acc[4][4];
#pragma unroll
        for (int i = 0; i < 4; i++)
#pragma unroll
            for (int j = 0; j < 4; j++) acc[i][j] = 0ull;

#pragma unroll 4
        for (int k4 = 0; k4 < 16; k4++) {
            ulonglong2 H0 = h0[k4], H1 = h1[k4], H2 = h2[k4], H3 = h3[k4];
            ulonglong2 W0 = w0[k4], W1 = w1[k4], W2 = w2[k4], W3 = w3[k4];
            fma2(acc[0][0], H0.x, W0.x); fma2(acc[0][0], H0.y, W0.y);
            fma2(acc[0][1], H0.x, W1.x); fma2(acc[0][1], H0.y, W1.y);
            fma2(acc[0][2], H0.x, W2.x); fma2(acc[0][2], H0.y, W2.y);
            fma2(acc[0][3], H0.x, W3.x); fma2(acc[0][3], H0.y, W3.y);
            fma2(acc[1][0], H1.x, W0.x); fma2(acc[1][0], H1.y, W0.y);
            fma2(acc[1][1], H1.x, W1.x); fma2(acc[1][1], H1.y, W1.y);
            fma2(acc[1][2], H1.x, W2.x); fma2(acc[1][2], H1.y, W2.y);
            fma2(acc[1][3], H1.x, W3.x); fma2(acc[1][3], H1.y, W3.y);
            fma2(acc[2][0], H2.x, W0.x); fma2(acc[2][0], H2.y, W0.y);
            fma2(acc[2][1], H2.x, W1.x); fma2(acc[2][1], H2.y, W1.y);
            fma2(acc[2][2], H2.x, W2.x); fma2(acc[2][2], H2.y, W2.y);
            fma2(acc[2][3], H2.x, W3.x); fma2(acc[2][3], H2.y, W3.y);
            fma2(acc[3][0], H3.x, W0.x); fma2(acc[3][0], H3.y, W0.y);
            fma2(acc[3][1], H3.x, W1.x); fma2(acc[3][1], H3.y, W1.y);
            fma2(acc[3][2], H3.x, W2.x); fma2(acc[3][2], H3.y, W2.y);
            fma2(acc[3][3], H3.x, W3.x); fma2(acc[3][3], H3.y, W3.y);
        }

        // ---- write k-eighth partials: p_s[b][r*8 + ks] ----
#pragma unroll
        for (int i = 0; i < 4; i++)
#pragma unroll
            for (int j = 0; j < 4; j++) {
                float2 p = unpack2(acc[i][j]);
                p_s[(bq + 8 * i) * PST + (rq + 8 * j) * 8 + ks] = p.x + p.y;
            }
        __syncthreads();

        // ---- activations + state update: threads 0..255 -> 32 b x 8 cols ----
        if (tid < 256) {
            float gs[4];
#pragma unroll
            for (int g = 0; g < 4; g++) {
                int r = g * 8 + ucl;
                float4 p0 = *(const float4*)(p_s + ub * PST + r * 8);
                float4 p1 = *(const float4*)(p_s + ub * PST + r * 8 + 4);
                gs[g] = ((p0.x + p0.y) + (p0.z + p0.w))
                      + ((p1.x + p1.y) + (p1.z + p1.w));
            }
            float ii = sigmoidf_(gs[0] + xi);
            float ff = sigmoidf_(gs[1] + xf);
            float gt = tanhf(gs[2] + xg);
            float oo = sigmoidf_(gs[3] + xo_);
            c_reg = ff * c_reg + ii * gt;
            float h = oo * tanhf(c_reg);
            g_h[dir][ph ^ 1][ub][ucol] = h;
            outbuf[((size_t)ub * SS + tt) * (2 * HH) + dir * HH + ucol] = h;
            __threadfence();              // release this thread's h writes
        }
        __syncthreads();

        // ---- arrive: parallel flag store (no atomics, no releaser) ----
        if (tid == 0) flags[cb] = (unsigned)(t + 1);
    }
}

// ===========================================================================
// Launch: per layer — init, 3 conversions, 2 mma GEMMs, 1 recurrence.
// ===========================================================================
extern "C" void kernel_launch(void* const* d_in, const int* in_sizes, int n_in,
                              void* d_out, int out_size)
{
    (void)in_sizes; (void)n_in; (void)out_size;

    const float* x     = (const float*)d_in[0];
    const float* wihf0 = (const float*)d_in[1];
    const float* bihf0 = (const float*)d_in[2];
    const float* whhf0 = (const float*)d_in[3];
    const float* wihb0 = (const float*)d_in[4];
    const float* bihb0 = (const float*)d_in[5];
    const float* whhb0 = (const float*)d_in[6];
    const float* wihf1 = (const float*)d_in[7];
    const float* bihf1 = (const float*)d_in[8];
    const float* whhf1 = (const float*)d_in[9];
    const float* wihb1 = (const float*)d_in[10];
    const float* bihb1 = (const float*)d_in[11];
    const float* whhb1 = (const float*)d_in[12];
    float* out = (float*)d_out;

    void* p = nullptr;
    cudaGetSymbolAddress(&p, g_xp);    float* xp   = (float*)p;
    cudaGetSymbolAddress(&p, g_out0);  float* out0 = (float*)p;
    cudaGetSymbolAddress(&p, g_a_hi);  __nv_bfloat16* ahi = (__nv_bfloat16*)p;
    cudaGetSymbolAddress(&p, g_a_lo);  __nv_bfloat16* alo = (__nv_bfloat16*)p;
    cudaGetSymbolAddress(&p, g_w_hi);  __nv_bfloat16* whi = (__nv_bfloat16*)p;
    cudaGetSymbolAddress(&p, g_w_lo);  __nv_bfloat16* wlo = (__nv_bfloat16*)p;

    const size_t STEP_SMEM = (size_t)(32 * HST + 32 * WST + 32 * PST) * sizeof(float);
    cudaFuncSetAttribute(lstm_layer_kernel,
                         cudaFuncAttributeMaxDynamicSharedMemorySize, (int)STEP_SMEM);
    cudaFuncSetAttribute(gemm_tc_kernel,
                         cudaFuncAttributeMaxDynamicSharedMemorySize, GSMEM);

    const dim3 tgrid(G4 / 256, (BB * SS) / 128);       // (8, 128)
    const size_t xp_stride = (size_t)SS * BB * G4;     // dir stride in g_xp
    const size_t wst = (size_t)G4 * 1024;              // dir stride in g_w_*
    const int init_blocks = (2 * 2 * BB * HH + 255) / 256;

    // ---------- layer 0 (K = 512) ----------
    init_state_kernel<<<init_blocks, 256>>>();
    conv_pair_kernel<<<(BB * SS * DD / 4 + 255) / 256, 256>>>(x, ahi, alo, BB * SS * DD / 4);
    conv_pair_kernel<<<(G4 * DD / 4 + 255) / 256, 256>>>(wihf0, whi, wlo, G4 * DD / 4);
    conv_pair_kernel<<<(G4 * DD / 4 + 255) / 256, 256>>>(wihb0, whi + wst, wlo + wst, G4 * DD / 4);
    gemm_tc_kernel<<<tgrid, 256, GSMEM>>>(ahi, alo, whi, wlo, bihf0, xp, DD);
    gemm_tc_kernel<<<tgrid, 256, GSMEM>>>(ahi, alo, whi + wst, wlo + wst, bihb0, xp + xp_stride, DD);
    lstm_layer_kernel<<<NBLK, NT, STEP_SMEM>>>(whhf0, whhb0, out0);

    // ---------- layer 1 (K = 1024) ----------
    init_state_kernel<<<init_blocks, 256>>>();
    conv_pair_kernel<<<(BB * SS * 2 * HH / 4 + 255) / 256, 256>>>(out0, ahi, alo, BB * SS * 2 * HH / 4);
    conv_pair_kernel<<<(G4 * 2 * HH / 4 + 255) / 256, 256>>>(wihf1, whi, wlo, G4 * 2 * HH / 4);
    conv_pair_kernel<<<(G4 * 2 * HH / 4 + 255) / 256, 256>>>(wihb1, whi + wst, wlo + wst, G4 * 2 * HH / 4);
    gemm_tc_kernel<<<tgrid, 256, GSMEM>>>(ahi, alo, whi, wlo, bihf1, xp, 2 * HH);
    gemm_tc_kernel<<<tgrid, 256, GSMEM>>>(ahi, alo, whi + wst, wlo + wst, bihb1, xp + xp_stride, 2 * HH);
    lstm_layer_kernel<<<NBLK, NT, STEP_SMEM>>>(whhf1, whhb1, out);
}

// round 15
// speedup vs baseline: 1.1487x; 1.1487x over previous
#include <cuda_runtime.h>
#include <cuda_bf16.h>
#include <cstdint>
#include <cstddef>
#include <math.h>

// Problem constants
#define BB 32
#define SS 512
#define DD 512
#define HH 512
#define G4 (4 * HH)     // 2048
#define NBLK 128        // persistent grid size (recurrence)
#define NBLK_DIR 64     // CTAs per direction
#define NT 512          // recurrence CTA threads

// ===========================================================================
// Small helpers
// ===========================================================================
__device__ __forceinline__ uint32_t smem_u32(const void* p)
{
    uint32_t a;
    asm("{ .reg .u64 t; cvta.to.shared.u64 t, %1; cvt.u32.u64 %0, t; }"
        : "=r"(a) : "l"(p));
    return a;
}

// ldmatrix x4 (four 8x8 b16 matrices)
__device__ __forceinline__ void ldsm4(uint32_t& r0, uint32_t& r1,
                                      uint32_t& r2, uint32_t& r3, uint32_t addr)
{
    asm volatile("ldmatrix.sync.aligned.m8n8.x4.shared.b16 {%0,%1,%2,%3}, [%4];"
                 : "=r"(r0), "=r"(r1), "=r"(r2), "=r"(r3) : "r"(addr));
}

// mma m16n8k16 bf16 -> f32
__device__ __forceinline__ void mma16816(float* c, const uint32_t* a,
                                         const uint32_t* b)
{
    asm volatile(
        "mma.sync.aligned.m16n8k16.row.col.f32.bf16.bf16.f32 "
        "{%0,%1,%2,%3}, {%4,%5,%6,%7}, {%8,%9}, {%0,%1,%2,%3};"
        : "+f"(c[0]), "+f"(c[1]), "+f"(c[2]), "+f"(c[3])
        : "r"(a[0]), "r"(a[1]), "r"(a[2]), "r"(a[3]), "r"(b[0]), "r"(b[1]));
}

__device__ __forceinline__ void cp_async16(uint32_t dst, const void* src)
{
    asm volatile("cp.async.cg.shared.global [%0], [%1], 16;"
                 :: "r"(dst), "l"(src) : "memory");
}

// Packed fp32x2 helpers (recurrence)
__device__ __forceinline__ void fma2(unsigned long long& d,
                                     unsigned long long a, unsigned long long b)
{
    asm("fma.rn.f32x2 %0, %1, %2, %0;" : "+l"(d) : "l"(a), "l"(b));
}
__device__ __forceinline__ float2 unpack2(unsigned long long v)
{
    float2 r;
    asm("mov.b64 {%0, %1}, %2;" : "=f"(r.x), "=f"(r.y) : "l"(v));
    return r;
}

// ===========================================================================
// Scratch (static __device__ arrays — no allocation allowed)
// ===========================================================================
__device__ float g_xp[2][SS][BB][G4];            // input projections [dir][s][b][g]
__device__ float g_out0[BB][SS][2 * HH];         // layer-0 output
__device__ float g_h[2][2][BB][HH];              // [dir][parity][b][h]
__device__ unsigned g_leaf[2][8][32];            // tree-barrier leaves (128B padded)
__device__ unsigned g_root[2][32];               // tree-barrier roots  (128B padded)
__device__ __nv_bfloat16 g_a_hi[16384 * 1024];   // A hi (max K=1024)
__device__ __nv_bfloat16 g_a_lo[16384 * 1024];   // A lo
__device__ __nv_bfloat16 g_w_hi[2][G4 * 1024];   // W hi per direction
__device__ __nv_bfloat16 g_w_lo[2][G4 * 1024];   // W lo per direction

// ---------------------------------------------------------------------------
// Zero h state + barrier counters
// ---------------------------------------------------------------------------
__global__ void __launch_bounds__(256) init_state_kernel()
{
    int i = blockIdx.x * 256 + threadIdx.x;
    if (i < 2 * 2 * BB * HH) (&g_h[0][0][0][0])[i] = 0.0f;
    if (i < 2 * 8 * 32)      (&g_leaf[0][0][0])[i] = 0u;
    if (i < 2 * 32)          (&g_root[0][0])[i]    = 0u;
}

// ---------------------------------------------------------------------------
// fp32 -> bf16 (hi, lo) split: x ≈ hi + lo, lo = rn(x - hi)
// ---------------------------------------------------------------------------
__global__ void __launch_bounds__(256) conv_pair_kernel(
    const float* __restrict__ src,
    __nv_bfloat16* __restrict__ hi, __nv_bfloat16* __restrict__ lo, int n4)
{
    int i = blockIdx.x * 256 + threadIdx.x;
    if (i >= n4) return;
    float4 v = ((const float4*)src)[i];
    __nv_bfloat16 h0 = __float2bfloat16(v.x);
    __nv_bfloat16 h1 = __float2bfloat16(v.y);
    __nv_bfloat16 h2 = __float2bfloat16(v.z);
    __nv_bfloat16 h3 = __float2bfloat16(v.w);
    __nv_bfloat16 l0 = __float2bfloat16(v.x - __bfloat162float(h0));
    __nv_bfloat16 l1 = __float2bfloat16(v.y - __bfloat162float(h1));
    __nv_bfloat16 l2 = __float2bfloat16(v.z - __bfloat162float(h2));
    __nv_bfloat16 l3 = __float2bfloat16(v.w - __bfloat162float(h3));
    ((__nv_bfloat162*)hi)[2 * i]     = __halves2bfloat162(h0, h1);
    ((__nv_bfloat162*)hi)[2 * i + 1] = __halves2bfloat162(h2, h3);
    ((__nv_bfloat162*)lo)[2 * i]     = __halves2bfloat162(l0, l1);
    ((__nv_bfloat162*)lo)[2 * i + 1] = __halves2bfloat162(l2, l3);
}

// ===========================================================================
// Tensor-core GEMM via mma.sync (3xBF16) — exact R12 version (best measured)
//   out[s*BB+b][n] = sum_k A(m,k)*W(n,k) + bias[n],  m = b*SS + s
// CTA 128(m) x 128(n), 8 warps (2x4), warp tile 64x32, K-chunks of 32.
// ===========================================================================
#define KC 32
#define TST 40                               // bf16 row stride (80 bytes)
#define TILE_B (128 * TST * 2)               // 10240 bytes per tile
#define BUFB (4 * TILE_B)                    // Ahi, Alo, Bhi, Blo = 40960
#define GSMEM (2 * BUFB)                     // 81920

__global__ void __launch_bounds__(256, 2) gemm_tc_kernel(
    const __nv_bfloat16* __restrict__ Ahi, const __nv_bfloat16* __restrict__ Alo,
    const __nv_bfloat16* __restrict__ Whi, const __nv_bfloat16* __restrict__ Wlo,
    const float* __restrict__ bias, float* __restrict__ out, int K)
{
    extern __shared__ char smem[];
    const int tid = threadIdx.x;
    const int wid = tid >> 5, lane = tid & 31;
    const int wm = wid >> 2, wn = wid & 3;       // 2 x 4 warp grid
    const int m0 = blockIdx.y * 128, n0 = blockIdx.x * 128;
    const uint32_t sb = smem_u32(smem);
    const int nch = K / KC;

    const int srow = tid >> 1;                   // 0..127
    const int sj   = (tid & 1) * 2;              // uint4 index 0 or 2
    const __nv_bfloat16* gbase[4] = {
        Ahi + (size_t)m0 * K, Alo + (size_t)m0 * K,
        Whi + (size_t)n0 * K, Wlo + (size_t)n0 * K };

    float acc[4][4][4];
#pragma unroll
    for (int i = 0; i < 4; i++)
#pragma unroll
        for (int j = 0; j < 4; j++)
#pragma unroll
            for (int r = 0; r < 4; r++) acc[i][j][r] = 0.0f;

    auto issue = [&](int c) {
        const uint32_t dst0 = sb + (c & 1) * BUFB + srow * 80 + sj * 16;
        const size_t go = (size_t)srow * K + c * KC + sj * 8;
#pragma unroll
        for (int t = 0; t < 4; t++) {
            cp_async16(dst0 + t * TILE_B,      gbase[t] + go);
            cp_async16(dst0 + t * TILE_B + 16, gbase[t] + go + 8);
        }
        asm volatile("cp.async.commit_group;" ::: "memory");
    };

    issue(0);
    if (nch > 1) issue(1);

    const uint32_t a_row = wm * 64 + (lane & 15);
    const uint32_t a_ko  = (lane >> 4) * 8;
    const uint32_t b_n   = wn * 32 + ((lane >> 4) << 3) + (lane & 7);
    const uint32_t b_ko  = ((lane >> 3) & 1) * 8;

    for (int c = 0; c < nch; c++) {
        if (c + 1 < nch) asm volatile("cp.async.wait_group 1;" ::: "memory");
        else             asm volatile("cp.async.wait_group 0;" ::: "memory");
        __syncthreads();

        const uint32_t ah = sb + (c & 1) * BUFB;
        const uint32_t al = ah + TILE_B;
        const uint32_t bh = ah + 2 * TILE_B;
        const uint32_t bl = ah + 3 * TILE_B;

#pragma unroll
        for (int kk = 0; kk < 2; kk++) {
            uint32_t Bh[8], Bl[8];
#pragma unroll
            for (int jj = 0; jj < 2; jj++) {
                uint32_t addr = (b_n + jj * 16) * 80 + (kk * 16 + b_ko) * 2;
                ldsm4(Bh[4 * jj], Bh[4 * jj + 1], Bh[4 * jj + 2], Bh[4 * jj + 3], bh + addr);
                ldsm4(Bl[4 * jj], Bl[4 * jj + 1], Bl[4 * jj + 2], Bl[4 * jj + 3], bl + addr);
            }
#pragma unroll
            for (int i = 0; i < 4; i++) {
                uint32_t addr = (a_row + i * 16) * 80 + (kk * 16 + a_ko) * 2;
                uint32_t Ah[4], Al[4];
                ldsm4(Ah[0], Ah[1], Ah[2], Ah[3], ah + addr);
                ldsm4(Al[0], Al[1], Al[2], Al[3], al + addr);
#pragma unroll
                for (int j = 0; j < 4; j++) {
                    mma16816(acc[i][j], Ah, Bh + 2 * j);
                    mma16816(acc[i][j], Ah, Bl + 2 * j);
                    mma16816(acc[i][j], Al, Bh + 2 * j);
                }
            }
        }
        __syncthreads();
        if (c + 2 < nch) issue(c + 2);
    }

#pragma unroll
    for (int i = 0; i < 4; i++) {
        const int r = m0 + wm * 64 + i * 16 + (lane >> 2);   // m = b*SS + s
        const int s_ = r & 511, b_ = r >> 9;
        float* p0 = out + ((size_t)s_ * BB + b_) * G4;
        float* p1 = p0 + (size_t)8 * BB * G4;                // row r+8 -> s+8
#pragma unroll
        for (int j = 0; j < 4; j++) {
            const int col = n0 + wn * 32 + j * 8 + (lane & 3) * 2;
            float2 bv = *(const float2*)(bias + col);
            float2 v0 = { acc[i][j][0] + bv.x, acc[i][j][1] + bv.y };
            float2 v1 = { acc[i][j][2] + bv.x, acc[i][j][3] + bv.y };
            *(float2*)(p0 + col) = v0;
            *(float2*)(p1 + col) = v1;
        }
    }
}

// ---------------------------------------------------------------------------
// Two-level monotonic tree barrier, per direction.
// Arrive: fence -> atomicAdd(leaf[group]); 8th arriver of a group adds 8 to
// the root. Wait: thread 0 polls root >= 64*(t+1). Leaves/roots 128B-padded
// (no false sharing); counters monotonic (zeroed per layer by init kernel).
// Fence pattern identical to the proven R12 barrier (one fence, thread 0).
// ---------------------------------------------------------------------------
__device__ __forceinline__ void grid_barrier(int dir, int cb, int t)
{
    __syncthreads();
    if (threadIdx.x == 0) {
        __threadfence();
        unsigned old = atomicAdd(&g_leaf[dir][cb >> 3][0], 1u);
        if ((old & 7u) == 7u)
            atomicAdd(&g_root[dir][0], 8u);
        volatile unsigned* r = &g_root[dir][0];
        const unsigned target = 64u * (unsigned)(t + 1);
        while (*r < target) { }
        __threadfence();
    }
    __syncthreads();
}

// ---------------------------------------------------------------------------
// Persistent per-layer LSTM recurrence (R12 body, tree barrier).
// ---------------------------------------------------------------------------
__device__ __forceinline__ float sigmoidf_(float x) { return 1.0f / (1.0f + expf(-x)); }

#define HST 516
#define WST 516
#define PST 260

__global__ void __launch_bounds__(NT) lstm_layer_kernel(
    const float* __restrict__ whh_f, const float* __restrict__ whh_b,
    float* __restrict__ outbuf)
{
    extern __shared__ float sm[];
    float* h_s = sm;                      // [32][HST]
    float* w_s = sm + 32 * HST;           // [32][WST]
    float* p_s = w_s + 32 * WST;          // [32][PST]

    const int dir  = blockIdx.x >> 6;
    const int cb   = blockIdx.x & 63;
    const int col0 = cb * 8;
    const int tid  = threadIdx.x;
    const float* whh = dir ? whh_b : whh_f;

    // ---- stage 32 weight rows ONCE: row r = gate*8 + cl ----
#pragma unroll
    for (int i = 0; i < 8; i++) {
        int n = tid + i * NT;
        int r = n >> 7, k4 = n & 127;
        int gate = r >> 3, cl = r & 7;
        float4 v = *(const float4*)(whh + ((size_t)gate * HH + col0 + cl) * HH + k4 * 4);
        *(float4*)(w_s + r * WST + k4 * 4) = v;
    }

    const int ks = tid >> 6;
    const int lo = tid & 63;
    const int bq = lo >> 3;
    const int rq = lo & 7;
    const int kk0 = ks * 16;

    const int ub = tid >> 3, ucl = tid & 7, ucol = col0 + ucl;
    float c_reg = 0.0f;
    const float* xbase = &g_xp[dir][0][0][0];

    for (int t = 0; t < SS; t++) {
        const int ph = t & 1;
        const int tt = dir ? (SS - 1 - t) : t;

        // ---- xp prefetch (overlaps h staging + dot) ----
        float xi = 0.f, xf = 0.f, xg = 0.f, xo_ = 0.f;
        if (tid < 256) {
            const size_t xo = ((size_t)tt * BB + ub) * G4 + ucol;
            xi  = __ldg(xbase + xo);
            xf  = __ldg(xbase + xo + HH);
            xg  = __ldg(xbase + xo + 2 * HH);
            xo_ = __ldg(xbase + xo + 3 * HH);
        }

        // ---- stage h_prev into padded smem (L2 loads bypass L1) ----
        {
            const float4* hp = (const float4*)&g_h[dir][ph][0][0];
#pragma unroll
            for (int i = 0; i < 8; i++) {
                int n = tid + i * NT;
                float4 v = __ldcg(hp + n);
                int b = n >> 7, k4 = n & 127;
                *(float4*)(h_s + b * HST + k4 * 4) = v;
            }
        }
        __syncthreads();

        // ---- 4x4 register micro-tile over this thread's k-eighth ----
        const ulonglong2* h0 = (const ulonglong2*)(h_s + (bq     ) * HST) + kk0;
        const ulonglong2* h1 = (const ulonglong2*)(h_s + (bq +  8) * HST) + kk0;
        const ulonglong2* h2 = (const ulonglong2*)(h_s + (bq + 16) * HST) + kk0;
        const ulonglong2* h3 = (const ulonglong2*)(h_s + (bq + 24) * HST) + kk0;
        const ulonglong2* w0 = (const ulonglong2*)(w_s + (rq     ) * WST) + kk0;
        const ulonglong2* w1 = (const ulonglong2*)(w_s + (rq +  8) * WST) + kk0;
        const ulonglong2* w2 = (const ulonglong2*)(w_s + (rq + 16) * WST) + kk0;
        const ulonglong2* w3 = (const ulonglong2*)(w_s + (rq + 24) * WST) + kk0;

        unsigned long long acc[4][4];
#pragma unroll
        for (int i = 0; i < 4; i++)
#pragma unroll
            for (int j = 0; j < 4; j++) acc[i][j] = 0ull;

#pragma unroll 4
        for (int k4 = 0; k4 < 16; k4++) {
            ulonglong2 H0 = h0[k4], H1 = h1[k4], H2 = h2[k4], H3 = h3[k4];
            ulonglong2 W0 = w0[k4], W1 = w1[k4], W2 = w2[k4], W3 = w3[k4];
            fma2(acc[0][0], H0.x, W0.x); fma2(acc[0][0], H0.y, W0.y);
            fma2(acc[0][1], H0.x, W1.x); fma2(acc[0][1], H0.y, W1.y);
            fma2(acc[0][2], H0.x, W2.x); fma2(acc[0][2], H0.y, W2.y);
            fma2(acc[0][3], H0.x, W3.x); fma2(acc[0][3], H0.y, W3.y);
            fma2(acc[1][0], H1.x, W0.x); fma2(acc[1][0], H1.y, W0.y);
            fma2(acc[1][1], H1.x, W1.x); fma2(acc[1][1], H1.y, W1.y);
            fma2(acc[1][2], H1.x, W2.x); fma2(acc[1][2], H1.y, W2.y);
            fma2(acc[1][3], H1.x, W3.x); fma2(acc[1][3], H1.y, W3.y);
            fma2(acc[2][0], H2.x, W0.x); fma2(acc[2][0], H2.y, W0.y);
            fma2(acc[2][1], H2.x, W1.x); fma2(acc[2][1], H2.y, W1.y);
            fma2(acc[2][2], H2.x, W2.x); fma2(acc[2][2], H2.y, W2.y);
            fma2(acc[2][3], H2.x, W3.x); fma2(acc[2][3], H2.y, W3.y);
            fma2(acc[3][0], H3.x, W0.x); fma2(acc[3][0], H3.y, W0.y);
            fma2(acc[3][1], H3.x, W1.x); fma2(acc[3][1], H3.y, W1.y);
            fma2(acc[3][2], H3.x, W2.x); fma2(acc[3][2], H3.y, W2.y);
            fma2(acc[3][3], H3.x, W3.x); fma2(acc[3][3], H3.y, W3.y);
        }

        // ---- write k-eighth partials: p_s[b][r*8 + ks] ----
#pragma unroll
        for (int i = 0; i < 4; i++)
#pragma unroll
            for (int j = 0; j < 4; j++) {
                float2 p = unpack2(acc[i][j]);
                p_s[(bq + 8 * i) * PST + (rq + 8 * j) * 8 + ks] = p.x + p.y;
            }
        __syncthreads();

        // ---- activations + state update: threads 0..255 -> 32 b x 8 cols ----
        if (tid < 256) {
            float gs[4];
#pragma unroll
            for (int g = 0; g < 4; g++) {
                int r = g * 8 + ucl;
                float4 p0 = *(const float4*)(p_s + ub * PST + r * 8);
                float4 p1 = *(const float4*)(p_s + ub * PST + r * 8 + 4);
                gs[g] = ((p0.x + p0.y) + (p0.z + p0.w))
                      + ((p1.x + p1.y) + (p1.z + p1.w));
            }
            float ii = sigmoidf_(gs[0] + xi);
            float ff = sigmoidf_(gs[1] + xf);
            float gt = tanhf(gs[2] + xg);
            float oo = sigmoidf_(gs[3] + xo_);
            c_reg = ff * c_reg + ii * gt;
            float h = oo * tanhf(c_reg);
            g_h[dir][ph ^ 1][ub][ucol] = h;
            outbuf[((size_t)ub * SS + tt) * (2 * HH) + dir * HH + ucol] = h;
        }

        // ---- per-direction tree barrier ----
        grid_barrier(dir, cb, t);
    }
}

// ===========================================================================
// Launch: per layer — init, 3 conversions, 2 mma GEMMs, 1 recurrence.
// ===========================================================================
extern "C" void kernel_launch(void* const* d_in, const int* in_sizes, int n_in,
                              void* d_out, int out_size)
{
    (void)in_sizes; (void)n_in; (void)out_size;

    const float* x     = (const float*)d_in[0];
    const float* wihf0 = (const float*)d_in[1];
    const float* bihf0 = (const float*)d_in[2];
    const float* whhf0 = (const float*)d_in[3];
    const float* wihb0 = (const float*)d_in[4];
    const float* bihb0 = (const float*)d_in[5];
    const float* whhb0 = (const float*)d_in[6];
    const float* wihf1 = (const float*)d_in[7];
    const float* bihf1 = (const float*)d_in[8];
    const float* whhf1 = (const float*)d_in[9];
    const float* wihb1 = (const float*)d_in[10];
    const float* bihb1 = (const float*)d_in[11];
    const float* whhb1 = (const float*)d_in[12];
    float* out = (float*)d_out;

    void* p = nullptr;
    cudaGetSymbolAddress(&p, g_xp);    float* xp   = (float*)p;
    cudaGetSymbolAddress(&p, g_out0);  float* out0 = (float*)p;
    cudaGetSymbolAddress(&p, g_a_hi);  __nv_bfloat16* ahi = (__nv_bfloat16*)p;
    cudaGetSymbolAddress(&p, g_a_lo);  __nv_bfloat16* alo = (__nv_bfloat16*)p;
    cudaGetSymbolAddress(&p, g_w_hi);  __nv_bfloat16* whi = (__nv_bfloat16*)p;
    cudaGetSymbolAddress(&p, g_w_lo);  __nv_bfloat16* wlo = (__nv_bfloat16*)p;

    const size_t STEP_SMEM = (size_t)(32 * HST + 32 * WST + 32 * PST) * sizeof(float);
    cudaFuncSetAttribute(lstm_layer_kernel,
                         cudaFuncAttributeMaxDynamicSharedMemorySize, (int)STEP_SMEM);
    cudaFuncSetAttribute(gemm_tc_kernel,
                         cudaFuncAttributeMaxDynamicSharedMemorySize, GSMEM);

    const dim3 tgrid(G4 / 128, (BB * SS) / 128);       // (16, 128)
    const size_t xp_stride = (size_t)SS * BB * G4;     // dir stride in g_xp
    const size_t wst = (size_t)G4 * 1024;              // dir stride in g_w_*
    const int init_blocks = (2 * 2 * BB * HH + 255) / 256;

    // ---------- layer 0 (K = 512) ----------
    init_state_kernel<<<init_blocks, 256>>>();
    conv_pair_kernel<<<(BB * SS * DD / 4 + 255) / 256, 256>>>(x, ahi, alo, BB * SS * DD / 4);
    conv_pair_kernel<<<(G4 * DD / 4 + 255) / 256, 256>>>(wihf0, whi, wlo, G4 * DD / 4);
    conv_pair_kernel<<<(G4 * DD / 4 + 255) / 256, 256>>>(wihb0, whi + wst, wlo + wst, G4 * DD / 4);
    gemm_tc_kernel<<<tgrid, 256, GSMEM>>>(ahi, alo, whi, wlo, bihf0, xp, DD);
    gemm_tc_kernel<<<tgrid, 256, GSMEM>>>(ahi, alo, whi + wst, wlo + wst, bihb0, xp + xp_stride, DD);
    lstm_layer_kernel<<<NBLK, NT, STEP_SMEM>>>(whhf0, whhb0, out0);

    // ---------- layer 1 (K = 1024) ----------
    init_state_kernel<<<init_blocks, 256>>>();
    conv_pair_kernel<<<(BB * SS * 2 * HH / 4 + 255) / 256, 256>>>(out0, ahi, alo, BB * SS * 2 * HH / 4);
    conv_pair_kernel<<<(G4 * 2 * HH / 4 + 255) / 256, 256>>>(wihf1, whi, wlo, G4 * 2 * HH / 4);
    conv_pair_kernel<<<(G4 * 2 * HH / 4 + 255) / 256, 256>>>(wihb1, whi + wst, wlo + wst, G4 * 2 * HH / 4);
    gemm_tc_kernel<<<tgrid, 256, GSMEM>>>(ahi, alo, whi, wlo, bihf1, xp, 2 * HH);
    gemm_tc_kernel<<<tgrid, 256, GSMEM>>>(ahi, alo, whi + wst, wlo + wst, bihb1, xp + xp_stride, 2 * HH);
    lstm_layer_kernel<<<NBLK, NT, STEP_SMEM>>>(whhf1, whhb1, out);
}

// round 17
// speedup vs baseline: 1.6164x; 1.4072x over previous
#include <cuda_runtime.h>
#include <cuda_bf16.h>
#include <cstdint>
#include <cstddef>
#include <math.h>

// Problem constants
#define BB 32
#define SS 512
#define DD 512
#define HH 512
#define G4 (4 * HH)     // 2048
#define NBLK 128        // persistent grid size (recurrence)
#define NBLK_DIR 64     // CTAs per direction
#define NT 512          // recurrence CTA threads

// ===========================================================================
// Small helpers
// ===========================================================================
__device__ __forceinline__ uint32_t smem_u32(const void* p)
{
    uint32_t a;
    asm("{ .reg .u64 t; cvta.to.shared.u64 t, %1; cvt.u32.u64 %0, t; }"
        : "=r"(a) : "l"(p));
    return a;
}

// ldmatrix x4 (four 8x8 b16 matrices)
__device__ __forceinline__ void ldsm4(uint32_t& r0, uint32_t& r1,
                                      uint32_t& r2, uint32_t& r3, uint32_t addr)
{
    asm volatile("ldmatrix.sync.aligned.m8n8.x4.shared.b16 {%0,%1,%2,%3}, [%4];"
                 : "=r"(r0), "=r"(r1), "=r"(r2), "=r"(r3) : "r"(addr));
}

// mma m16n8k16 bf16 -> f32
__device__ __forceinline__ void mma16816(float* c, const uint32_t* a,
                                         const uint32_t* b)
{
    asm volatile(
        "mma.sync.aligned.m16n8k16.row.col.f32.bf16.bf16.f32 "
        "{%0,%1,%2,%3}, {%4,%5,%6,%7}, {%8,%9}, {%0,%1,%2,%3};"
        : "+f"(c[0]), "+f"(c[1]), "+f"(c[2]), "+f"(c[3])
        : "r"(a[0]), "r"(a[1]), "r"(a[2]), "r"(a[3]), "r"(b[0]), "r"(b[1]));
}

__device__ __forceinline__ void cp_async16(uint32_t dst, const void* src)
{
    asm volatile("cp.async.cg.shared.global [%0], [%1], 16;"
                 :: "r"(dst), "l"(src) : "memory");
}

// ===========================================================================
// Scratch (static __device__ arrays — no allocation allowed)
// ===========================================================================
__device__ float g_xp[2][SS][BB][G4];              // input projections [dir][s][b][g]
__device__ float g_out0[BB][SS][2 * HH];           // layer-0 output
__device__ __nv_bfloat16 g_h_hi[2][2][BB][HH];     // h hi, [dir][parity][b][h]
__device__ __nv_bfloat16 g_h_lo[2][2][BB][HH];     // h lo
__device__ unsigned g_leaf[2][8][32];              // tree-barrier leaves (padded)
__device__ unsigned g_root[2][32];                 // tree-barrier roots  (padded)
__device__ __nv_bfloat16 g_a_hi[16384 * 1024];     // GEMM A hi (max K=1024)
__device__ __nv_bfloat16 g_a_lo[16384 * 1024];     // GEMM A lo
__device__ __nv_bfloat16 g_w_hi[2][G4 * 1024];     // GEMM W hi per direction
__device__ __nv_bfloat16 g_w_lo[2][G4 * 1024];     // GEMM W lo per direction

// ---------------------------------------------------------------------------
// Zero h state + barrier counters
// ---------------------------------------------------------------------------
__global__ void __launch_bounds__(256) init_state_kernel()
{
    int i = blockIdx.x * 256 + threadIdx.x;
    if (i < 2 * 2 * BB * HH) {
        (&g_h_hi[0][0][0][0])[i] = __float2bfloat16(0.0f);
        (&g_h_lo[0][0][0][0])[i] = __float2bfloat16(0.0f);
    }
    if (i < 2 * 8 * 32) (&g_leaf[0][0][0])[i] = 0u;
    if (i < 2 * 32)     (&g_root[0][0])[i]    = 0u;
}

// ---------------------------------------------------------------------------
// fp32 -> bf16 (hi, lo) split: x ≈ hi + lo, lo = rn(x - hi)
// ---------------------------------------------------------------------------
__global__ void __launch_bounds__(256) conv_pair_kernel(
    const float* __restrict__ src,
    __nv_bfloat16* __restrict__ hi, __nv_bfloat16* __restrict__ lo, int n4)
{
    int i = blockIdx.x * 256 + threadIdx.x;
    if (i >= n4) return;
    float4 v = ((const float4*)src)[i];
    __nv_bfloat16 h0 = __float2bfloat16(v.x);
    __nv_bfloat16 h1 = __float2bfloat16(v.y);
    __nv_bfloat16 h2 = __float2bfloat16(v.z);
    __nv_bfloat16 h3 = __float2bfloat16(v.w);
    __nv_bfloat16 l0 = __float2bfloat16(v.x - __bfloat162float(h0));
    __nv_bfloat16 l1 = __float2bfloat16(v.y - __bfloat162float(h1));
    __nv_bfloat16 l2 = __float2bfloat16(v.z - __bfloat162float(h2));
    __nv_bfloat16 l3 = __float2bfloat16(v.w - __bfloat162float(h3));
    ((__nv_bfloat162*)hi)[2 * i]     = __halves2bfloat162(h0, h1);
    ((__nv_bfloat162*)hi)[2 * i + 1] = __halves2bfloat162(h2, h3);
    ((__nv_bfloat162*)lo)[2 * i]     = __halves2bfloat162(l0, l1);
    ((__nv_bfloat162*)lo)[2 * i + 1] = __halves2bfloat162(l2, l3);
}

// ===========================================================================
// Tensor-core GEMM via mma.sync (3xBF16) — exact R12 version (best measured)
// ===========================================================================
#define KC 32
#define TST 40                               // bf16 row stride (80 bytes)
#define TILE_B (128 * TST * 2)               // 10240 bytes per tile
#define BUFB (4 * TILE_B)                    // Ahi, Alo, Bhi, Blo = 40960
#define GSMEM (2 * BUFB)                     // 81920

__global__ void __launch_bounds__(256, 2) gemm_tc_kernel(
    const __nv_bfloat16* __restrict__ Ahi, const __nv_bfloat16* __restrict__ Alo,
    const __nv_bfloat16* __restrict__ Whi, const __nv_bfloat16* __restrict__ Wlo,
    const float* __restrict__ bias, float* __restrict__ out, int K)
{
    extern __shared__ char smem[];
    const int tid = threadIdx.x;
    const int wid = tid >> 5, lane = tid & 31;
    const int wm = wid >> 2, wn = wid & 3;       // 2 x 4 warp grid
    const int m0 = blockIdx.y * 128, n0 = blockIdx.x * 128;
    const uint32_t sb = smem_u32(smem);
    const int nch = K / KC;

    const int srow = tid >> 1;                   // 0..127
    const int sj   = (tid & 1) * 2;              // uint4 index 0 or 2
    const __nv_bfloat16* gbase[4] = {
        Ahi + (size_t)m0 * K, Alo + (size_t)m0 * K,
        Whi + (size_t)n0 * K, Wlo + (size_t)n0 * K };

    float acc[4][4][4];
#pragma unroll
    for (int i = 0; i < 4; i++)
#pragma unroll
        for (int j = 0; j < 4; j++)
#pragma unroll
            for (int r = 0; r < 4; r++) acc[i][j][r] = 0.0f;

    auto issue = [&](int c) {
        const uint32_t dst0 = sb + (c & 1) * BUFB + srow * 80 + sj * 16;
        const size_t go = (size_t)srow * K + c * KC + sj * 8;
#pragma unroll
        for (int t = 0; t < 4; t++) {
            cp_async16(dst0 + t * TILE_B,      gbase[t] + go);
            cp_async16(dst0 + t * TILE_B + 16, gbase[t] + go + 8);
        }
        asm volatile("cp.async.commit_group;" ::: "memory");
    };

    issue(0);
    if (nch > 1) issue(1);

    const uint32_t a_row = wm * 64 + (lane & 15);
    const uint32_t a_ko  = (lane >> 4) * 8;
    const uint32_t b_n   = wn * 32 + ((lane >> 4) << 3) + (lane & 7);
    const uint32_t b_ko  = ((lane >> 3) & 1) * 8;

    for (int c = 0; c < nch; c++) {
        if (c + 1 < nch) asm volatile("cp.async.wait_group 1;" ::: "memory");
        else             asm volatile("cp.async.wait_group 0;" ::: "memory");
        __syncthreads();

        const uint32_t ah = sb + (c & 1) * BUFB;
        const uint32_t al = ah + TILE_B;
        const uint32_t bh = ah + 2 * TILE_B;
        const uint32_t bl = ah + 3 * TILE_B;

#pragma unroll
        for (int kk = 0; kk < 2; kk++) {
            uint32_t Bh[8], Bl[8];
#pragma unroll
            for (int jj = 0; jj < 2; jj++) {
                uint32_t addr = (b_n + jj * 16) * 80 + (kk * 16 + b_ko) * 2;
                ldsm4(Bh[4 * jj], Bh[4 * jj + 1], Bh[4 * jj + 2], Bh[4 * jj + 3], bh + addr);
                ldsm4(Bl[4 * jj], Bl[4 * jj + 1], Bl[4 * jj + 2], Bl[4 * jj + 3], bl + addr);
            }
#pragma unroll
            for (int i = 0; i < 4; i++) {
                uint32_t addr = (a_row + i * 16) * 80 + (kk * 16 + a_ko) * 2;
                uint32_t Ah[4], Al[4];
                ldsm4(Ah[0], Ah[1], Ah[2], Ah[3], ah + addr);
                ldsm4(Al[0], Al[1], Al[2], Al[3], al + addr);
#pragma unroll
                for (int j = 0; j < 4; j++) {
                    mma16816(acc[i][j], Ah, Bh + 2 * j);
                    mma16816(acc[i][j], Ah, Bl + 2 * j);
                    mma16816(acc[i][j], Al, Bh + 2 * j);
                }
            }
        }
        __syncthreads();
        if (c + 2 < nch) issue(c + 2);
    }

#pragma unroll
    for (int i = 0; i < 4; i++) {
        const int r = m0 + wm * 64 + i * 16 + (lane >> 2);   // m = b*SS + s
        const int s_ = r & 511, b_ = r >> 9;
        float* p0 = out + ((size_t)s_ * BB + b_) * G4;
        float* p1 = p0 + (size_t)8 * BB * G4;                // row r+8 -> s+8
#pragma unroll
        for (int j = 0; j < 4; j++) {
            const int col = n0 + wn * 32 + j * 8 + (lane & 3) * 2;
            float2 bv = *(const float2*)(bias + col);
            float2 v0 = { acc[i][j][0] + bv.x, acc[i][j][1] + bv.y };
            float2 v1 = { acc[i][j][2] + bv.x, acc[i][j][3] + bv.y };
            *(float2*)(p0 + col) = v0;
            *(float2*)(p1 + col) = v1;
        }
    }
}

// ---------------------------------------------------------------------------
// Two-level monotonic tree barrier, per direction (R15, proven).
// ---------------------------------------------------------------------------
__device__ __forceinline__ void grid_barrier(int dir, int cb, int t)
{
    __syncthreads();
    if (threadIdx.x == 0) {
        __threadfence();
        unsigned old = atomicAdd(&g_leaf[dir][cb >> 3][0], 1u);
        if ((old & 7u) == 7u)
            atomicAdd(&g_root[dir][0], 8u);
        volatile unsigned* r = &g_root[dir][0];
        const unsigned target = 64u * (unsigned)(t + 1);
        while (*r < target) { }
        __threadfence();
    }
    __syncthreads();
}

// ---------------------------------------------------------------------------
// Persistent per-layer LSTM recurrence — tensor-core dot phase.
// Grid: 128 CTAs = [dir(2) x colblock(64)], 8 cols per CTA, 512 threads.
// Step gates[32b][32r] = h[32b][512k] @ w[32r][512k]^T via mma.sync 3xBF16:
// h transported as bf16 hi/lo (written by the update phase — no per-step
// conversion), w converted to hi/lo smem tiles once. Warp (kg, mh) computes
// m16 x n32 over its 64-k group; partials land in the same p_s[b][r*8+kg]
// layout the (unchanged) update phase consumes. Tree barrier per step.
// R17 fix: h staging copies the FULL 2048-chunk tile (i<4, b=n>>6, c=n&63);
// R16 only staged half of it to wrong offsets.
// ---------------------------------------------------------------------------
__device__ __forceinline__ float sigmoidf_(float x) { return 1.0f / (1.0f + expf(-x)); }

#define RSTB 1040     // smem row stride BYTES (1040 % 128 == 16 -> conflict-free ldsm)
#define RTILE (32 * RSTB)            // 33280 B per hi/lo tile
#define PST 260                      // p_s row stride (floats)
#define RSMEM (4 * RTILE + 32 * PST * 4)   // h_hi,h_lo,w_hi,w_lo + p_s = 166400

__global__ void __launch_bounds__(NT) lstm_layer_kernel(
    const float* __restrict__ whh_f, const float* __restrict__ whh_b,
    float* __restrict__ outbuf)
{
    extern __shared__ char smc[];
    char* h_hi = smc;                       // [32][RSTB]
    char* h_lo = smc + RTILE;
    char* w_hi = smc + 2 * RTILE;
    char* w_lo = smc + 3 * RTILE;
    float* p_s = (float*)(smc + 4 * RTILE); // [32][PST]

    const int dir  = blockIdx.x >> 6;
    const int cb   = blockIdx.x & 63;
    const int col0 = cb * 8;
    const int tid  = threadIdx.x;
    const int wid  = tid >> 5, lane = tid & 31;
    const float* whh = dir ? whh_b : whh_f;
    const uint32_t sb = smem_u32(smc);

    // ---- convert 32 weight rows ONCE to bf16 hi/lo (row r = gate*8 + cl) ----
#pragma unroll
    for (int i = 0; i < 8; i++) {
        int n = tid + i * NT;               // 4096 = 32 rows x 128 float4
        int r = n >> 7, k4 = n & 127;
        int gate = r >> 3, cl = r & 7;
        float4 v = *(const float4*)(whh + ((size_t)gate * HH + col0 + cl) * HH + k4 * 4);
        __nv_bfloat16 a0 = __float2bfloat16(v.x), a1 = __float2bfloat16(v.y);
        __nv_bfloat16 a2 = __float2bfloat16(v.z), a3 = __float2bfloat16(v.w);
        __nv_bfloat162 hi0 = __halves2bfloat162(a0, a1);
        __nv_bfloat162 hi1 = __halves2bfloat162(a2, a3);
        __nv_bfloat162 lo0 = __halves2bfloat162(
            __float2bfloat16(v.x - __bfloat162float(a0)),
            __float2bfloat16(v.y - __bfloat162float(a1)));
        __nv_bfloat162 lo1 = __halves2bfloat162(
            __float2bfloat16(v.z - __bfloat162float(a2)),
            __float2bfloat16(v.w - __bfloat162float(a3)));
        char* dh = w_hi + r * RSTB + k4 * 8;
        char* dl = w_lo + r * RSTB + k4 * 8;
        ((__nv_bfloat162*)dh)[0] = hi0; ((__nv_bfloat162*)dh)[1] = hi1;
        ((__nv_bfloat162*)dl)[0] = lo0; ((__nv_bfloat162*)dl)[1] = lo1;
    }

    // warp roles for the MMA phase
    const int kg = wid >> 1;                // k-group 0..7 (64 k each)
    const int mh = wid & 1;                 // m half (16 batches)
    const uint32_t a_r  = (lane & 15);
    const uint32_t a_ko = (lane >> 4) * 8;
    const uint32_t b_n  = ((lane >> 4) << 3) + (lane & 7);
    const uint32_t b_ko = ((lane >> 3) & 1) * 8;

    // update-phase role (threads 0..255): thread owns (ub, ucol)
    const int ub = tid >> 3, ucl = tid & 7, ucol = col0 + ucl;
    float c_reg = 0.0f;
    const float* xbase = &g_xp[dir][0][0][0];

    for (int t = 0; t < SS; t++) {
        const int ph = t & 1;
        const int tt = dir ? (SS - 1 - t) : t;

        // ---- xp prefetch (overlaps staging + MMA) ----
        float xi = 0.f, xf = 0.f, xg = 0.f, xo_ = 0.f;
        if (tid < 256) {
            const size_t xo = ((size_t)tt * BB + ub) * G4 + ucol;
            xi  = __ldg(xbase + xo);
            xf  = __ldg(xbase + xo + HH);
            xg  = __ldg(xbase + xo + 2 * HH);
            xo_ = __ldg(xbase + xo + 3 * HH);
        }

        // ---- stage h hi/lo: FULL tile = 2048 16B chunks each ----
        // chunk n: row b = n>>6 (64 chunks per 1024B row), chunk c = n&63
        {
            const uint4* sh = (const uint4*)&g_h_hi[dir][ph][0][0];
            const uint4* sl = (const uint4*)&g_h_lo[dir][ph][0][0];
#pragma unroll
            for (int i = 0; i < 4; i++) {
                int n = tid + i * NT;       // 0..2047
                int b = n >> 6, c = n & 63;
                *(uint4*)(h_hi + b * RSTB + c * 16) = __ldcg(sh + n);
                *(uint4*)(h_lo + b * RSTB + c * 16) = __ldcg(sl + n);
            }
        }
        __syncthreads();

        // ---- MMA: warp (kg, mh): m16(b) x n32(r) over k in [kg*64, kg*64+64) ----
        float acc[4][4];
#pragma unroll
        for (int j = 0; j < 4; j++)
#pragma unroll
            for (int r = 0; r < 4; r++) acc[j][r] = 0.0f;

        const uint32_t hh = sb + mh * 16 * RSTB;
        const uint32_t hl = hh + RTILE;
        const uint32_t wh = sb + 2 * RTILE;
        const uint32_t wl = sb + 3 * RTILE;

#pragma unroll
        for (int kc = 0; kc < 4; kc++) {
            const uint32_t kb = (kg * 4 + kc) * 16;
            uint32_t Ah[4], Al[4];
            {
                uint32_t addr = a_r * RSTB + (kb + a_ko) * 2;
                ldsm4(Ah[0], Ah[1], Ah[2], Ah[3], hh + addr);
                ldsm4(Al[0], Al[1], Al[2], Al[3], hl + addr);
            }
            uint32_t Bh[8], Bl[8];
#pragma unroll
            for (int jj = 0; jj < 2; jj++) {
                uint32_t addr = (b_n + jj * 16) * RSTB + (kb + b_ko) * 2;
                ldsm4(Bh[4 * jj], Bh[4 * jj + 1], Bh[4 * jj + 2], Bh[4 * jj + 3], wh + addr);
                ldsm4(Bl[4 * jj], Bl[4 * jj + 1], Bl[4 * jj + 2], Bl[4 * jj + 3], wl + addr);
            }
#pragma unroll
            for (int j = 0; j < 4; j++) {
                mma16816(acc[j], Ah, Bh + 2 * j);
                mma16816(acc[j], Ah, Bl + 2 * j);
                mma16816(acc[j], Al, Bh + 2 * j);
            }
        }

        // ---- store partials: p_s[b][r*8 + kg] ----
        {
            const int brow = mh * 16 + (lane >> 2);
            const int rcol = (lane & 3) * 2;
#pragma unroll
            for (int j = 0; j < 4; j++) {
                const int r0 = j * 8 + rcol;
                p_s[brow * PST + r0 * 8 + kg]             = acc[j][0];
                p_s[brow * PST + (r0 + 1) * 8 + kg]       = acc[j][1];
                p_s[(brow + 8) * PST + r0 * 8 + kg]       = acc[j][2];
                p_s[(brow + 8) * PST + (r0 + 1) * 8 + kg] = acc[j][3];
            }
        }
        __syncthreads();

        // ---- activations + state update: threads 0..255 -> 32 b x 8 cols ----
        if (tid < 256) {
            float gs[4];
#pragma unroll
            for (int g = 0; g < 4; g++) {
                int r = g * 8 + ucl;
                float4 p0 = *(const float4*)(p_s + ub * PST + r * 8);
                float4 p1 = *(const float4*)(p_s + ub * PST + r * 8 + 4);
                gs[g] = ((p0.x + p0.y) + (p0.z + p0.w))
                      + ((p1.x + p1.y) + (p1.z + p1.w));
            }
            float ii = sigmoidf_(gs[0] + xi);
            float ff = sigmoidf_(gs[1] + xf);
            float gt = tanhf(gs[2] + xg);
            float oo = sigmoidf_(gs[3] + xo_);
            c_reg = ff * c_reg + ii * gt;
            float h = oo * tanhf(c_reg);
            __nv_bfloat16 hh_ = __float2bfloat16(h);
            __nv_bfloat16 hl_ = __float2bfloat16(h - __bfloat162float(hh_));
            g_h_hi[dir][ph ^ 1][ub][ucol] = hh_;
            g_h_lo[dir][ph ^ 1][ub][ucol] = hl_;
            outbuf[((size_t)ub * SS + tt) * (2 * HH) + dir * HH + ucol] = h;
        }

        // ---- per-direction tree barrier ----
        grid_barrier(dir, cb, t);
    }
}

// ===========================================================================
// Launch: per layer — init, 3 conversions, 2 mma GEMMs, 1 recurrence.
// ===========================================================================
extern "C" void kernel_launch(void* const* d_in, const int* in_sizes, int n_in,
                              void* d_out, int out_size)
{
    (void)in_sizes; (void)n_in; (void)out_size;

    const float* x     = (const float*)d_in[0];
    const float* wihf0 = (const float*)d_in[1];
    const float* bihf0 = (const float*)d_in[2];
    const float* whhf0 = (const float*)d_in[3];
    const float* wihb0 = (const float*)d_in[4];
    const float* bihb0 = (const float*)d_in[5];
    const float* whhb0 = (const float*)d_in[6];
    const float* wihf1 = (const float*)d_in[7];
    const float* bihf1 = (const float*)d_in[8];
    const float* whhf1 = (const float*)d_in[9];
    const float* wihb1 = (const float*)d_in[10];
    const float* bihb1 = (const float*)d_in[11];
    const float* whhb1 = (const float*)d_in[12];
    float* out = (float*)d_out;

    void* p = nullptr;
    cudaGetSymbolAddress(&p, g_xp);    float* xp   = (float*)p;
    cudaGetSymbolAddress(&p, g_out0);  float* out0 = (float*)p;
    cudaGetSymbolAddress(&p, g_a_hi);  __nv_bfloat16* ahi = (__nv_bfloat16*)p;
    cudaGetSymbolAddress(&p, g_a_lo);  __nv_bfloat16* alo = (__nv_bfloat16*)p;
    cudaGetSymbolAddress(&p, g_w_hi);  __nv_bfloat16* whi = (__nv_bfloat16*)p;
    cudaGetSymbolAddress(&p, g_w_lo);  __nv_bfloat16* wlo = (__nv_bfloat16*)p;

    cudaFuncSetAttribute(lstm_layer_kernel,
                         cudaFuncAttributeMaxDynamicSharedMemorySize, RSMEM);
    cudaFuncSetAttribute(gemm_tc_kernel,
                         cudaFuncAttributeMaxDynamicSharedMemorySize, GSMEM);

    const dim3 tgrid(G4 / 128, (BB * SS) / 128);       // (16, 128)
    const size_t xp_stride = (size_t)SS * BB * G4;     // dir stride in g_xp
    const size_t wst = (size_t)G4 * 1024;              // dir stride in g_w_*
    const int init_blocks = (2 * 2 * BB * HH + 255) / 256;

    // ---------- layer 0 (K = 512) ----------
    init_state_kernel<<<init_blocks, 256>>>();
    conv_pair_kernel<<<(BB * SS * DD / 4 + 255) / 256, 256>>>(x, ahi, alo, BB * SS * DD / 4);
    conv_pair_kernel<<<(G4 * DD / 4 + 255) / 256, 256>>>(wihf0, whi, wlo, G4 * DD / 4);
    conv_pair_kernel<<<(G4 * DD / 4 + 255) / 256, 256>>>(wihb0, whi + wst, wlo + wst, G4 * DD / 4);
    gemm_tc_kernel<<<tgrid, 256, GSMEM>>>(ahi, alo, whi, wlo, bihf0, xp, DD);
    gemm_tc_kernel<<<tgrid, 256, GSMEM>>>(ahi, alo, whi + wst, wlo + wst, bihb0, xp + xp_stride, DD);
    lstm_layer_kernel<<<NBLK, NT, RSMEM>>>(whhf0, whhb0, out0);

    // ---------- layer 1 (K = 1024) ----------
    init_state_kernel<<<init_blocks, 256>>>();
    conv_pair_kernel<<<(BB * SS * 2 * HH / 4 + 255) / 256, 256>>>(out0, ahi, alo, BB * SS * 2 * HH / 4);
    conv_pair_kernel<<<(G4 * 2 * HH / 4 + 255) / 256, 256>>>(wihf1, whi, wlo, G4 * 2 * HH / 4);
    conv_pair_kernel<<<(G4 * 2 * HH / 4 + 255) / 256, 256>>>(wihb1, whi + wst, wlo + wst, G4 * 2 * HH / 4);
    gemm_tc_kernel<<<tgrid, 256, GSMEM>>>(ahi, alo, whi, wlo, bihf1, xp, 2 * HH);
    gemm_tc_kernel<<<tgrid, 256, GSMEM>>>(ahi, alo, whi + wst, wlo + wst, bihb1, xp + xp_stride, 2 * HH);
    lstm_layer_kernel<<<NBLK, NT, RSMEM>>>(whhf1, whhb1, out);
}